// round 1
// baseline (speedup 1.0000x reference)
#include <cuda_runtime.h>
#include <cuda_bf16.h>

// Problem constants
#define PP 2048      // selected rows
#define HH 1024      // hidden
#define AA 16        // branches
#define OO 4         // outputs per branch
#define BB 4096      // batch

// GEMM tiling
#define BM 128
#define BN 128
#define BK 16
#define ASTR 132     // padded A-tile stride (conflict-free scatter stores)

typedef unsigned long long ull;

// ---------------- packed f32x2 helpers (sm_103a) ----------------
__device__ __forceinline__ ull pack2(float lo, float hi) {
    ull r; asm("mov.b64 %0, {%1, %2};" : "=l"(r) : "f"(lo), "f"(hi)); return r;
}
__device__ __forceinline__ void unpack2(ull v, float& lo, float& hi) {
    asm("mov.b64 {%0, %1}, %2;" : "=f"(lo), "=f"(hi) : "l"(v));
}
__device__ __forceinline__ void fma2(ull& d, ull a, ull b) {
    asm("fma.rn.f32x2 %0, %1, %2, %0;" : "+l"(d) : "l"(a), "l"(b));
}

// ---------------- device scratch (allocation-free) ----------------
__device__ float g_Xg [PP * HH];
__device__ float g_X1g[PP * HH];
__device__ float g_Z  [(long)AA * PP * HH];
__device__ float g_Hh [(long)AA * PP * HH];

// ---------------- gather kernel ----------------
__global__ void gather_kernel(const float* __restrict__ X,
                              const float* __restrict__ X1,
                              const int* __restrict__ pos,
                              float* __restrict__ Xg,
                              float* __restrict__ X1g) {
    int p = blockIdx.x;
    int tid = threadIdx.x;          // 256 threads, 4 floats each
    int r = pos[p];
    ((float4*)(Xg  + (long)p * HH))[tid] = ((const float4*)(X  + (long)r * HH))[tid];
    ((float4*)(X1g + (long)p * HH))[tid] = ((const float4*)(X1 + (long)r * HH))[tid];
}

// ---------------- fp32 tiled GEMM with f32x2 FMA ----------------
// C[a] = A1[a] @ B1[a] (+ A2[a] @ B2[a]) + bias1[a] (+ bias2[a]) ; optional ReLU
// M=PP, N=HH, K=HH. A row-major lda=K, B row-major ldb=N, C row-major ldc=N.
template<int NIN, bool RELU>
__global__ __launch_bounds__(256, 2)
void gemm_kernel(const float* __restrict__ A1, long strideA,
                 const float* __restrict__ B1w,
                 const float* __restrict__ A2,
                 const float* __restrict__ B2w,
                 const float* __restrict__ bias1,
                 const float* __restrict__ bias2,
                 float* __restrict__ Cout) {
    const int K = HH, N = HH;
    const int a  = blockIdx.z;
    const int m0 = blockIdx.x * BM;
    const int n0 = blockIdx.y * BN;

    __shared__ float As[BK * ASTR];
    __shared__ float Bs[BK * BN];

    const int tid  = threadIdx.x;
    const int tRow = tid >> 4;   // 0..15
    const int tCol = tid & 15;   // 0..15

    ull acc[8][4];
#pragma unroll
    for (int i = 0; i < 8; ++i)
#pragma unroll
        for (int j = 0; j < 4; ++j) acc[i][j] = 0ull;

#pragma unroll 1
    for (int pair = 0; pair < NIN; ++pair) {
        const float* Ag = ((pair == 0) ? A1 : A2) + (long)a * strideA;
        const float* Bg = ((pair == 0) ? B1w : B2w) + (long)a * ((long)K * N);

#pragma unroll 1
        for (int k0 = 0; k0 < K; k0 += BK) {
            __syncthreads();
            // A tile: BM x BK, store transposed into As[k][m]
#pragma unroll
            for (int u = 0; u < 2; ++u) {
                int idx = tid + u * 256;          // 0..511
                int row = idx >> 2;               // 0..127
                int c4  = (idx & 3) * 4;          // 0,4,8,12
                float4 v = *(const float4*)&Ag[(long)(m0 + row) * K + k0 + c4];
                As[(c4 + 0) * ASTR + row] = v.x;
                As[(c4 + 1) * ASTR + row] = v.y;
                As[(c4 + 2) * ASTR + row] = v.z;
                As[(c4 + 3) * ASTR + row] = v.w;
            }
            // B tile: BK x BN
#pragma unroll
            for (int u = 0; u < 2; ++u) {
                int idx = tid + u * 256;
                int kr  = idx >> 5;               // 0..15
                int c4  = (idx & 31) * 4;         // 0..124
                *(float4*)&Bs[kr * BN + c4] =
                    *(const float4*)&Bg[(long)(k0 + kr) * N + n0 + c4];
            }
            __syncthreads();

#pragma unroll
            for (int k = 0; k < BK; ++k) {
                float4 a0 = *(const float4*)&As[k * ASTR + tRow * 4];
                float4 a1 = *(const float4*)&As[k * ASTR + 64 + tRow * 4];
                float4 b0 = *(const float4*)&Bs[k * BN + tCol * 4];
                float4 b1 = *(const float4*)&Bs[k * BN + 64 + tCol * 4];
                ull rb[4] = { pack2(b0.x, b0.y), pack2(b0.z, b0.w),
                              pack2(b1.x, b1.y), pack2(b1.z, b1.w) };
                float ra[8] = { a0.x, a0.y, a0.z, a0.w, a1.x, a1.y, a1.z, a1.w };
#pragma unroll
                for (int i = 0; i < 8; ++i) {
                    ull av = pack2(ra[i], ra[i]);
#pragma unroll
                    for (int j = 0; j < 4; ++j) fma2(acc[i][j], av, rb[j]);
                }
            }
        }
    }

    // epilogue: bias (+bias2), optional relu, store
    float4 bb0 = *(const float4*)&bias1[(long)a * N + n0 + tCol * 4];
    float4 bb1 = *(const float4*)&bias1[(long)a * N + n0 + 64 + tCol * 4];
    if (NIN == 2) {
        float4 c0 = *(const float4*)&bias2[(long)a * N + n0 + tCol * 4];
        float4 c1 = *(const float4*)&bias2[(long)a * N + n0 + 64 + tCol * 4];
        bb0.x += c0.x; bb0.y += c0.y; bb0.z += c0.z; bb0.w += c0.w;
        bb1.x += c1.x; bb1.y += c1.y; bb1.z += c1.z; bb1.w += c1.w;
    }
    float* Cp = Cout + (long)a * ((long)PP * N);
#pragma unroll
    for (int i = 0; i < 8; ++i) {
        int m = m0 + ((i < 4) ? (tRow * 4 + i) : (64 + tRow * 4 + (i - 4)));
        float c[8];
        unpack2(acc[i][0], c[0], c[1]); unpack2(acc[i][1], c[2], c[3]);
        unpack2(acc[i][2], c[4], c[5]); unpack2(acc[i][3], c[6], c[7]);
        c[0] += bb0.x; c[1] += bb0.y; c[2] += bb0.z; c[3] += bb0.w;
        c[4] += bb1.x; c[5] += bb1.y; c[6] += bb1.z; c[7] += bb1.w;
        if (RELU) {
#pragma unroll
            for (int j = 0; j < 8; ++j) c[j] = fmaxf(c[j], 0.0f);
        }
        *(float4*)&Cp[(long)m * N + n0 + tCol * 4]      = make_float4(c[0], c[1], c[2], c[3]);
        *(float4*)&Cp[(long)m * N + n0 + 64 + tCol * 4] = make_float4(c[4], c[5], c[6], c[7]);
    }
}

// ---------------- fused LayerNorm + W4 projection + output ----------------
__global__ void ln_out_kernel(const float* __restrict__ Hb,
                              const float* __restrict__ gamma,
                              const float* __restrict__ beta,
                              const float* __restrict__ W4,
                              const float* __restrict__ b4,
                              float* __restrict__ out) {
    const int p = blockIdx.x;
    const int a = blockIdx.y;
    const int tid = threadIdx.x;   // 256
    const int warp = tid >> 5, lane = tid & 31;

    const float* hrow = Hb + ((long)a * PP + p) * HH;
    float4 hv = ((const float4*)hrow)[tid];

    float s  = hv.x + hv.y + hv.z + hv.w;
    float s2 = hv.x * hv.x + hv.y * hv.y + hv.z * hv.z + hv.w * hv.w;
#pragma unroll
    for (int o = 16; o; o >>= 1) {
        s  += __shfl_xor_sync(0xFFFFFFFFu, s,  o);
        s2 += __shfl_xor_sync(0xFFFFFFFFu, s2, o);
    }
    __shared__ float red0[8], red1[8];
    if (lane == 0) { red0[warp] = s; red1[warp] = s2; }
    __syncthreads();
    float ts = 0.f, ts2 = 0.f;
#pragma unroll
    for (int w = 0; w < 8; ++w) { ts += red0[w]; ts2 += red1[w]; }
    float mu  = ts * (1.0f / HH);
    float var = ts2 * (1.0f / HH) - mu * mu;
    float inv = rsqrtf(var + 1e-5f);

    float4 g  = ((const float4*)(gamma + (long)a * HH))[tid];
    float4 be = ((const float4*)(beta  + (long)a * HH))[tid];
    float hn[4];
    hn[0] = (hv.x - mu) * inv * g.x + be.x;
    hn[1] = (hv.y - mu) * inv * g.y + be.y;
    hn[2] = (hv.z - mu) * inv * g.z + be.z;
    hn[3] = (hv.w - mu) * inv * g.w + be.w;

    const float4* w4 = (const float4*)(W4 + (long)a * HH * OO); // [H][4] rows
    int i0 = tid * 4;
    float4 acc = make_float4(0.f, 0.f, 0.f, 0.f);
#pragma unroll
    for (int e = 0; e < 4; ++e) {
        float4 w = w4[i0 + e];
        acc.x += hn[e] * w.x; acc.y += hn[e] * w.y;
        acc.z += hn[e] * w.z; acc.w += hn[e] * w.w;
    }
#pragma unroll
    for (int o = 16; o; o >>= 1) {
        acc.x += __shfl_xor_sync(0xFFFFFFFFu, acc.x, o);
        acc.y += __shfl_xor_sync(0xFFFFFFFFu, acc.y, o);
        acc.z += __shfl_xor_sync(0xFFFFFFFFu, acc.z, o);
        acc.w += __shfl_xor_sync(0xFFFFFFFFu, acc.w, o);
    }
    __shared__ float4 racc[8];
    if (lane == 0) racc[warp] = acc;
    __syncthreads();
    if (tid == 0) {
        float4 t = racc[0];
#pragma unroll
        for (int w = 1; w < 8; ++w) {
            t.x += racc[w].x; t.y += racc[w].y; t.z += racc[w].z; t.w += racc[w].w;
        }
        long ob = (long)p * (AA * OO) + a * OO;
        out[ob + 0] = t.x + b4[a * OO + 0];
        out[ob + 1] = t.y + b4[a * OO + 1];
        out[ob + 2] = t.z + b4[a * OO + 2];
        out[ob + 3] = t.w + b4[a * OO + 3];
    }
}

// ---------------- launch ----------------
extern "C" void kernel_launch(void* const* d_in, const int* in_sizes, int n_in,
                              void* d_out, int out_size) {
    const float* X     = (const float*)d_in[0];
    const float* X1    = (const float*)d_in[1];
    const float* W1    = (const float*)d_in[2];
    const float* b1    = (const float*)d_in[3];
    const float* W2    = (const float*)d_in[4];
    const float* b2    = (const float*)d_in[5];
    const float* W3    = (const float*)d_in[6];
    const float* b3    = (const float*)d_in[7];
    const float* gamma = (const float*)d_in[8];
    const float* beta  = (const float*)d_in[9];
    const float* W4    = (const float*)d_in[10];
    const float* b4    = (const float*)d_in[11];
    const int*   pos   = (const int*)d_in[12];
    float* out = (float*)d_out;

    float *pXg, *pX1g, *pZ, *pH;
    cudaGetSymbolAddress((void**)&pXg,  g_Xg);
    cudaGetSymbolAddress((void**)&pX1g, g_X1g);
    cudaGetSymbolAddress((void**)&pZ,   g_Z);
    cudaGetSymbolAddress((void**)&pH,   g_Hh);

    gather_kernel<<<PP, 256>>>(X, X1, pos, pXg, pX1g);

    dim3 gg(PP / BM, HH / BN, AA);   // (16, 8, 16)
    // Z = Xg@W1 + X1g@W2 + b1 + b2
    gemm_kernel<2, false><<<gg, 256>>>(pXg, 0L, W1, pX1g, W2, b1, b2, pZ);
    // H = relu(Z@W3 + b3)
    gemm_kernel<1, true><<<gg, 256>>>(pZ, (long)PP * HH, W3, nullptr, nullptr, b3, nullptr, pH);
    // LayerNorm + W4 + b4 -> out[p, a*4+o]
    ln_out_kernel<<<dim3(PP, AA), 256>>>(pH, gamma, beta, W4, b4, out);
}

// round 3
// speedup vs baseline: 2.1691x; 2.1691x over previous
#include <cuda_runtime.h>
#include <cstdint>

#define PP 2048
#define HH 1024
#define AA 16
#define OO 4

#define BM 128
#define BN 128
#define BK 32

// SMEM per stage (floats): A 128x36 padded, B 32x132 padded
#define ASZ (128 * 36)
#define BSZ (32 * 132)
#define SMEM_FLOATS (2 * (ASZ + BSZ))
#define SMEM_BYTES  (SMEM_FLOATS * 4)

// ---------------- device scratch ----------------
__device__ float g_Xg [PP * HH];
__device__ float g_X1g[PP * HH];
__device__ float g_Z  [(long long)AA * PP * HH];
__device__ float g_gw [AA * HH * OO];
__device__ float g_Gco[AA * OO];
__device__ float g_Bco[AA * OO];
__device__ float g_part[(long long)AA * 8 * PP * 8];   // [a][ntile 0..7][p][8]

// ---------------- helpers ----------------
__device__ __forceinline__ uint32_t smem_u32(const void* p) {
    uint32_t a;
    asm("{ .reg .u64 t; cvta.to.shared.u64 t, %1; cvt.u32.u64 %0, t; }" : "=r"(a) : "l"(p));
    return a;
}
__device__ __forceinline__ void cp16(uint32_t s, const void* g) {
    asm volatile("cp.async.cg.shared.global [%0], [%1], 16;" :: "r"(s), "l"(g));
}
__device__ __forceinline__ void cp_commit() {
    asm volatile("cp.async.commit_group;" ::: "memory");
}
template <int N>
__device__ __forceinline__ void cp_wait() {
    asm volatile("cp.async.wait_group %0;" :: "n"(N) : "memory");
}
__device__ __forceinline__ uint32_t f2tf(float v) {
    uint32_t r;
    asm("cvt.rna.tf32.f32 %0, %1;" : "=r"(r) : "f"(v));
    return r;
}
__device__ __forceinline__ void mma_tf32(float c[4], const uint32_t a[4], const uint32_t b[2]) {
    asm volatile(
        "mma.sync.aligned.m16n8k8.row.col.f32.tf32.tf32.f32 "
        "{%0,%1,%2,%3}, {%4,%5,%6,%7}, {%8,%9}, {%0,%1,%2,%3};"
        : "+f"(c[0]), "+f"(c[1]), "+f"(c[2]), "+f"(c[3])
        : "r"(a[0]), "r"(a[1]), "r"(a[2]), "r"(a[3]), "r"(b[0]), "r"(b[1]));
}

// ---------------- gather ----------------
__global__ void gather_kernel(const float* __restrict__ X, const float* __restrict__ X1,
                              const int* __restrict__ pos,
                              float* __restrict__ Xg, float* __restrict__ X1g) {
    int p = blockIdx.x, tid = threadIdx.x;
    int r = pos[p];
    ((float4*)(Xg  + (long long)p * HH))[tid] = ((const float4*)(X  + (long long)r * HH))[tid];
    ((float4*)(X1g + (long long)p * HH))[tid] = ((const float4*)(X1 + (long long)r * HH))[tid];
}

// ---------------- prep: gw = gamma*W4 ; Gco = sum gamma*W4 ; Bco = sum beta*W4 + b4 ----------------
__global__ void prep_kernel(const float* __restrict__ gamma, const float* __restrict__ beta,
                            const float* __restrict__ W4, const float* __restrict__ b4,
                            float* __restrict__ gw, float* __restrict__ Gco, float* __restrict__ Bco) {
    __shared__ float red[8][256];
    int a = blockIdx.x, tid = threadIdx.x;
    float G[4] = {0, 0, 0, 0}, Bc[4] = {0, 0, 0, 0};
    for (int h = tid; h < HH; h += 256) {
        float g = gamma[a * HH + h], be = beta[a * HH + h];
        float4 w = *(const float4*)&W4[((long long)a * HH + h) * 4];
        float4 r = make_float4(g * w.x, g * w.y, g * w.z, g * w.w);
        *(float4*)&gw[((long long)a * HH + h) * 4] = r;
        G[0] += r.x; G[1] += r.y; G[2] += r.z; G[3] += r.w;
        Bc[0] += be * w.x; Bc[1] += be * w.y; Bc[2] += be * w.z; Bc[3] += be * w.w;
    }
#pragma unroll
    for (int j = 0; j < 4; ++j) { red[j][tid] = G[j]; red[4 + j][tid] = Bc[j]; }
    __syncthreads();
    for (int s = 128; s > 0; s >>= 1) {
        if (tid < s)
#pragma unroll
            for (int j = 0; j < 8; ++j) red[j][tid] += red[j][tid + s];
        __syncthreads();
    }
    if (tid < 4) {
        Gco[a * 4 + tid] = red[tid][0];
        Bco[a * 4 + tid] = red[4 + tid][0] + b4[a * 4 + tid];
    }
}

// ---------------- tf32 mma.sync GEMM ----------------
// DUAL:  C = A1@W1 + A2@W2 (A per-row shared over a; W per-a), epilogue adds b1+b2, writes Z
// !DUAL: C = Z[a]@W3, epilogue relu(+b3) reduced to partials (sum, sumsq, sum*gw)
template <bool DUAL, bool REDUCE>
__global__ void __launch_bounds__(256, 2)
gemm_mma(const float* __restrict__ A1, const float* __restrict__ A2,
         const float* __restrict__ B1, const float* __restrict__ B2,
         long long strideA,
         const float* __restrict__ bias1, const float* __restrict__ bias2,
         const float* __restrict__ gw,
         float* __restrict__ outZ, float* __restrict__ part) {
    extern __shared__ float sm[];
    float* Asb[2] = { sm, sm + ASZ };
    float* Bsb[2] = { sm + 2 * ASZ, sm + 2 * ASZ + BSZ };
    uint32_t sA[2] = { smem_u32(Asb[0]), smem_u32(Asb[1]) };
    uint32_t sB[2] = { smem_u32(Bsb[0]), smem_u32(Bsb[1]) };

    const int tid = threadIdx.x, lane = tid & 31, wid = tid >> 5;
    const int g = lane >> 2, t = lane & 3;
    const int wm = (wid >> 2) * 64, wn = (wid & 3) * 32;
    const int m0 = blockIdx.x * BM, n0 = blockIdx.y * BN, a = blockIdx.z;
    const int NIT = DUAL ? 64 : 32;

    float c[4][4][4];
#pragma unroll
    for (int i = 0; i < 4; ++i)
#pragma unroll
        for (int j = 0; j < 4; ++j)
#pragma unroll
            for (int q = 0; q < 4; ++q) c[i][j][q] = 0.f;

    // ---- stage loader ----
    auto load_stage = [&](int it) {
        int buf = it & 1;
        int pr = DUAL ? (it >> 5) : 0;
        int k0 = DUAL ? (it & 31) * BK : it * BK;
        const float* Ag = DUAL ? (pr ? A2 : A1) : (A1 + (long long)a * strideA);
        const float* Bg = ((DUAL && pr) ? B2 : B1) + (long long)a * HH * HH;
#pragma unroll
        for (int u = 0; u < 4; ++u) {
            int idx = tid + u * 256;
            int m = idx >> 3, kq = idx & 7;
            cp16(sA[buf] + (uint32_t)(m * 36 + kq * 4) * 4,
                 Ag + (long long)(m0 + m) * HH + k0 + kq * 4);
        }
#pragma unroll
        for (int u = 0; u < 4; ++u) {
            int idx = tid + u * 256;
            int k = idx >> 5, nq = idx & 31;
            cp16(sB[buf] + (uint32_t)(k * 132 + nq * 4) * 4,
                 Bg + (long long)(k0 + k) * HH + n0 + nq * 4);
        }
        cp_commit();
    };

    load_stage(0);
#pragma unroll 1
    for (int it = 0; it < NIT; ++it) {
        if (it + 1 < NIT) { load_stage(it + 1); cp_wait<1>(); }
        else              { cp_wait<0>(); }
        __syncthreads();
        int buf = it & 1;
        const float* As = Asb[buf];
        const float* Bs = Bsb[buf];
#pragma unroll
        for (int ks = 0; ks < 4; ++ks) {
            uint32_t af[4][4], bf[4][2];
#pragma unroll
            for (int i = 0; i < 4; ++i) {
                int r0 = wm + i * 16 + g;
                int col = ks * 8 + t;
                af[i][0] = f2tf(As[r0 * 36 + col]);
                af[i][1] = f2tf(As[(r0 + 8) * 36 + col]);
                af[i][2] = f2tf(As[r0 * 36 + col + 4]);
                af[i][3] = f2tf(As[(r0 + 8) * 36 + col + 4]);
            }
#pragma unroll
            for (int j = 0; j < 4; ++j) {
                int nn = wn + j * 8 + g;
                bf[j][0] = f2tf(Bs[(ks * 8 + t) * 132 + nn]);
                bf[j][1] = f2tf(Bs[(ks * 8 + t + 4) * 132 + nn]);
            }
#pragma unroll
            for (int i = 0; i < 4; ++i)
#pragma unroll
                for (int j = 0; j < 4; ++j) mma_tf32(c[i][j], af[i], bf[j]);
        }
        __syncthreads();
    }

    if (!REDUCE) {
        // epilogue: + (b1+b2), store Z
#pragma unroll
        for (int j = 0; j < 4; ++j) {
            int col = n0 + wn + j * 8 + t * 2;
            float bx = bias1[a * HH + col]     + bias2[a * HH + col];
            float by = bias1[a * HH + col + 1] + bias2[a * HH + col + 1];
#pragma unroll
            for (int i = 0; i < 4; ++i) {
                int row = m0 + wm + i * 16 + g;
                float2 v0 = make_float2(c[i][j][0] + bx, c[i][j][1] + by);
                float2 v1 = make_float2(c[i][j][2] + bx, c[i][j][3] + by);
                *(float2*)&outZ[((long long)a * PP + row) * HH + col]     = v0;
                *(float2*)&outZ[((long long)a * PP + row + 8) * HH + col] = v1;
            }
        }
    } else {
        // epilogue: v = relu(c + b3); partials s1=sum v, s2=sum v^2, s3=sum v*gw
        float* red = sm;   // reuse SMEM: 128 rows x 8
        for (int idx = tid; idx < 128 * 8; idx += 256) red[idx] = 0.f;
        __syncthreads();
#pragma unroll
        for (int i = 0; i < 4; ++i) {
#pragma unroll
            for (int gs = 0; gs < 2; ++gs) {
                float s1 = 0.f, s2 = 0.f, sx = 0.f, sy = 0.f, sz = 0.f, sw = 0.f;
#pragma unroll
                for (int j = 0; j < 4; ++j) {
                    int col = n0 + wn + j * 8 + t * 2;
                    float v0 = fmaxf(c[i][j][gs * 2]     + bias1[a * HH + col],     0.f);
                    float v1 = fmaxf(c[i][j][gs * 2 + 1] + bias1[a * HH + col + 1], 0.f);
                    s1 += v0 + v1;
                    s2 += v0 * v0 + v1 * v1;
                    float4 g0 = *(const float4*)&gw[((long long)a * HH + col) * 4];
                    float4 g1 = *(const float4*)&gw[((long long)a * HH + col + 1) * 4];
                    sx += v0 * g0.x + v1 * g1.x;
                    sy += v0 * g0.y + v1 * g1.y;
                    sz += v0 * g0.z + v1 * g1.z;
                    sw += v0 * g0.w + v1 * g1.w;
                }
#pragma unroll
                for (int o = 1; o <= 2; o <<= 1) {
                    s1 += __shfl_xor_sync(0xFFFFFFFFu, s1, o);
                    s2 += __shfl_xor_sync(0xFFFFFFFFu, s2, o);
                    sx += __shfl_xor_sync(0xFFFFFFFFu, sx, o);
                    sy += __shfl_xor_sync(0xFFFFFFFFu, sy, o);
                    sz += __shfl_xor_sync(0xFFFFFFFFu, sz, o);
                    sw += __shfl_xor_sync(0xFFFFFFFFu, sw, o);
                }
                if (t == 0) {
                    int rl = wm + i * 16 + gs * 8 + g;
                    atomicAdd(&red[rl * 8 + 0], s1);
                    atomicAdd(&red[rl * 8 + 1], s2);
                    atomicAdd(&red[rl * 8 + 2], sx);
                    atomicAdd(&red[rl * 8 + 3], sy);
                    atomicAdd(&red[rl * 8 + 4], sz);
                    atomicAdd(&red[rl * 8 + 5], sw);
                }
            }
        }
        __syncthreads();
        for (int idx = tid; idx < 128 * 6; idx += 256) {
            int row = idx / 6, q = idx % 6;
            part[(((long long)a * 8 + blockIdx.y) * PP + (m0 + row)) * 8 + q] = red[row * 8 + q];
        }
    }
}

// ---------------- final: combine partials, closed-form LN + projection ----------------
__global__ void final_kernel(const float* __restrict__ part, const float* __restrict__ Gco,
                             const float* __restrict__ Bco, float* __restrict__ out) {
    int tk = blockIdx.x * 256 + threadIdx.x;   // 0..32767
    int p = tk >> 4, a = tk & 15;
    float s1 = 0.f, s2 = 0.f, so[4] = {0.f, 0.f, 0.f, 0.f};
#pragma unroll
    for (int nt = 0; nt < 8; ++nt) {
        const float* q = part + (((long long)a * 8 + nt) * PP + p) * 8;
        s1 += q[0]; s2 += q[1];
        so[0] += q[2]; so[1] += q[3]; so[2] += q[4]; so[3] += q[5];
    }
    float mu  = s1 * (1.0f / HH);
    float var = s2 * (1.0f / HH) - mu * mu;
    float inv = rsqrtf(var + 1e-5f);
    float4 o;
    o.x = (so[0] - mu * Gco[a * 4 + 0]) * inv + Bco[a * 4 + 0];
    o.y = (so[1] - mu * Gco[a * 4 + 1]) * inv + Bco[a * 4 + 1];
    o.z = (so[2] - mu * Gco[a * 4 + 2]) * inv + Bco[a * 4 + 2];
    o.w = (so[3] - mu * Gco[a * 4 + 3]) * inv + Bco[a * 4 + 3];
    ((float4*)out)[tk] = o;
}

// ---------------- host ----------------
extern "C" void kernel_launch(void* const* d_in, const int* in_sizes, int n_in,
                              void* d_out, int out_size) {
    const float* X     = (const float*)d_in[0];
    const float* X1    = (const float*)d_in[1];
    const float* W1    = (const float*)d_in[2];
    const float* b1    = (const float*)d_in[3];
    const float* W2    = (const float*)d_in[4];
    const float* b2    = (const float*)d_in[5];
    const float* W3    = (const float*)d_in[6];
    const float* b3    = (const float*)d_in[7];
    const float* gamma = (const float*)d_in[8];
    const float* beta  = (const float*)d_in[9];
    const float* W4    = (const float*)d_in[10];
    const float* b4    = (const float*)d_in[11];
    const int*   pos   = (const int*)d_in[12];
    float* out = (float*)d_out;

    float *pXg, *pX1g, *pZ, *pgw, *pGco, *pBco, *ppart;
    cudaGetSymbolAddress((void**)&pXg,   g_Xg);
    cudaGetSymbolAddress((void**)&pX1g,  g_X1g);
    cudaGetSymbolAddress((void**)&pZ,    g_Z);
    cudaGetSymbolAddress((void**)&pgw,   g_gw);
    cudaGetSymbolAddress((void**)&pGco,  g_Gco);
    cudaGetSymbolAddress((void**)&pBco,  g_Bco);
    cudaGetSymbolAddress((void**)&ppart, g_part);

    cudaFuncSetAttribute(gemm_mma<true,  false>, cudaFuncAttributeMaxDynamicSharedMemorySize, SMEM_BYTES);
    cudaFuncSetAttribute(gemm_mma<false, true >, cudaFuncAttributeMaxDynamicSharedMemorySize, SMEM_BYTES);

    gather_kernel<<<PP, 256>>>(X, X1, pos, pXg, pX1g);
    prep_kernel<<<AA, 256>>>(gamma, beta, W4, b4, pgw, pGco, pBco);

    dim3 gg(PP / BM, HH / BN, AA);   // (16, 8, 16)
    // Z = Xg@W1 + X1g@W2 + b1 + b2
    gemm_mma<true, false><<<gg, 256, SMEM_BYTES>>>(
        pXg, pX1g, W1, W2, 0LL, b1, b2, nullptr, pZ, nullptr);
    // partials of relu(Z@W3 + b3)
    gemm_mma<false, true><<<gg, 256, SMEM_BYTES>>>(
        pZ, nullptr, W3, nullptr, (long long)PP * HH, b3, nullptr, pgw, nullptr, ppart);
    // closed-form LN + projection
    final_kernel<<<(PP * AA) / 256, 256>>>(ppart, pGco, pBco, out);
}

// round 4
// speedup vs baseline: 2.3424x; 1.0799x over previous
#include <cuda_runtime.h>
#include <cstdint>

#define PP 2048
#define HH 1024
#define AA 16
#define OO 4

#define BM 128
#define BN 128
#define BK 32

// SMEM per stage (floats): A 128x36 padded, B 32x132 padded
#define ASZ (128 * 36)
#define BSZ (32 * 132)
#define SMEM_FLOATS (2 * (ASZ + BSZ))
#define SMEM_BYTES  (SMEM_FLOATS * 4)

// ---------------- device scratch ----------------
__device__ float g_Xg [PP * HH];
__device__ float g_X1g[PP * HH];
__device__ float g_W  [3ll * AA * HH * HH];            // tf32-rounded W1,W2,W3
__device__ float g_Z  [(long long)AA * PP * HH];
__device__ float g_gw [AA * HH * OO];
__device__ float g_Gco[AA * OO];
__device__ float g_Bco[AA * OO];
__device__ float g_part[(long long)AA * 8 * PP * 8];   // [a][ntile 0..7][p][8]

// ---------------- helpers ----------------
__device__ __forceinline__ uint32_t smem_u32(const void* p) {
    uint32_t a;
    asm("{ .reg .u64 t; cvta.to.shared.u64 t, %1; cvt.u32.u64 %0, t; }" : "=r"(a) : "l"(p));
    return a;
}
__device__ __forceinline__ void cp16(uint32_t s, const void* g) {
    asm volatile("cp.async.cg.shared.global [%0], [%1], 16;" :: "r"(s), "l"(g));
}
__device__ __forceinline__ void cp_commit() {
    asm volatile("cp.async.commit_group;" ::: "memory");
}
template <int N>
__device__ __forceinline__ void cp_wait() {
    asm volatile("cp.async.wait_group %0;" :: "n"(N) : "memory");
}
__device__ __forceinline__ float f2tf_f(float v) {
    uint32_t r;
    asm("cvt.rna.tf32.f32 %0, %1;" : "=r"(r) : "f"(v));
    return __uint_as_float(r);
}
__device__ __forceinline__ void mma_tf32(float c[4], const uint32_t a[4], const uint32_t b[2]) {
    asm volatile(
        "mma.sync.aligned.m16n8k8.row.col.f32.tf32.tf32.f32 "
        "{%0,%1,%2,%3}, {%4,%5,%6,%7}, {%8,%9}, {%0,%1,%2,%3};"
        : "+f"(c[0]), "+f"(c[1]), "+f"(c[2]), "+f"(c[3])
        : "r"(a[0]), "r"(a[1]), "r"(a[2]), "r"(a[3]), "r"(b[0]), "r"(b[1]));
}

// ---------------- gather (+ tf32 round) ----------------
__global__ void gather_kernel(const float* __restrict__ X, const float* __restrict__ X1,
                              const int* __restrict__ pos,
                              float* __restrict__ Xg, float* __restrict__ X1g) {
    int p = blockIdx.x, tid = threadIdx.x;
    int r = pos[p];
    float4 v0 = ((const float4*)(X  + (long long)r * HH))[tid];
    float4 v1 = ((const float4*)(X1 + (long long)r * HH))[tid];
    v0.x = f2tf_f(v0.x); v0.y = f2tf_f(v0.y); v0.z = f2tf_f(v0.z); v0.w = f2tf_f(v0.w);
    v1.x = f2tf_f(v1.x); v1.y = f2tf_f(v1.y); v1.z = f2tf_f(v1.z); v1.w = f2tf_f(v1.w);
    ((float4*)(Xg  + (long long)p * HH))[tid] = v0;
    ((float4*)(X1g + (long long)p * HH))[tid] = v1;
}

// ---------------- round weights to tf32 (streams; one float4 per thread) ----------------
__global__ void round_w_kernel(const float* __restrict__ W1, const float* __restrict__ W2,
                               const float* __restrict__ W3, float* __restrict__ Wd) {
    long long i = ((long long)blockIdx.x * 256 + threadIdx.x);     // float4 index
    const long long per = (long long)AA * HH * HH / 4;             // 4194304
    const float4* src = (i < per) ? (const float4*)W1
                       : (i < 2 * per) ? (const float4*)W2 : (const float4*)W3;
    long long off = i % per;
    float4 v = src[off];
    v.x = f2tf_f(v.x); v.y = f2tf_f(v.y); v.z = f2tf_f(v.z); v.w = f2tf_f(v.w);
    ((float4*)Wd)[i] = v;
}

// ---------------- prep: gw = gamma*W4 ; Gco = sum gamma*W4 ; Bco = sum beta*W4 + b4 ----------------
__global__ void prep_kernel(const float* __restrict__ gamma, const float* __restrict__ beta,
                            const float* __restrict__ W4, const float* __restrict__ b4,
                            float* __restrict__ gw, float* __restrict__ Gco, float* __restrict__ Bco) {
    __shared__ float red[8][256];
    int a = blockIdx.x, tid = threadIdx.x;
    float G[4] = {0, 0, 0, 0}, Bc[4] = {0, 0, 0, 0};
    for (int h = tid; h < HH; h += 256) {
        float g = gamma[a * HH + h], be = beta[a * HH + h];
        float4 w = *(const float4*)&W4[((long long)a * HH + h) * 4];
        float4 r = make_float4(g * w.x, g * w.y, g * w.z, g * w.w);
        *(float4*)&gw[((long long)a * HH + h) * 4] = r;
        G[0] += r.x; G[1] += r.y; G[2] += r.z; G[3] += r.w;
        Bc[0] += be * w.x; Bc[1] += be * w.y; Bc[2] += be * w.z; Bc[3] += be * w.w;
    }
#pragma unroll
    for (int j = 0; j < 4; ++j) { red[j][tid] = G[j]; red[4 + j][tid] = Bc[j]; }
    __syncthreads();
    for (int s = 128; s > 0; s >>= 1) {
        if (tid < s)
#pragma unroll
            for (int j = 0; j < 8; ++j) red[j][tid] += red[j][tid + s];
        __syncthreads();
    }
    if (tid < 4) {
        Gco[a * 4 + tid] = red[tid][0];
        Bco[a * 4 + tid] = red[4 + tid][0] + b4[a * 4 + tid];
    }
}

// ---------------- tf32 mma.sync GEMM (inputs pre-rounded; no cvt in loop) ----------------
template <bool DUAL, bool REDUCE>
__global__ void __launch_bounds__(256, 2)
gemm_mma(const float* __restrict__ A1, const float* __restrict__ A2,
         const float* __restrict__ B1, const float* __restrict__ B2,
         long long strideA,
         const float* __restrict__ bias1, const float* __restrict__ bias2,
         const float* __restrict__ gw,
         float* __restrict__ outZ, float* __restrict__ part) {
    extern __shared__ float sm[];
    float* Asb[2] = { sm, sm + ASZ };
    float* Bsb[2] = { sm + 2 * ASZ, sm + 2 * ASZ + BSZ };
    uint32_t sA[2] = { smem_u32(Asb[0]), smem_u32(Asb[1]) };
    uint32_t sB[2] = { smem_u32(Bsb[0]), smem_u32(Bsb[1]) };

    const int tid = threadIdx.x, lane = tid & 31, wid = tid >> 5;
    const int g = lane >> 2, t = lane & 3;
    const int wm = (wid >> 2) * 64, wn = (wid & 3) * 32;
    const int m0 = blockIdx.x * BM, n0 = blockIdx.y * BN, a = blockIdx.z;
    const int NIT = DUAL ? 64 : 32;

    float c[4][4][4];
#pragma unroll
    for (int i = 0; i < 4; ++i)
#pragma unroll
        for (int j = 0; j < 4; ++j)
#pragma unroll
            for (int q = 0; q < 4; ++q) c[i][j][q] = 0.f;

    auto load_stage = [&](int it) {
        int buf = it & 1;
        int pr = DUAL ? (it >> 5) : 0;
        int k0 = DUAL ? (it & 31) * BK : it * BK;
        const float* Ag = DUAL ? (pr ? A2 : A1) : (A1 + (long long)a * strideA);
        const float* Bg = ((DUAL && pr) ? B2 : B1) + (long long)a * HH * HH;
#pragma unroll
        for (int u = 0; u < 4; ++u) {
            int idx = tid + u * 256;
            int m = idx >> 3, kq = idx & 7;
            cp16(sA[buf] + (uint32_t)(m * 36 + kq * 4) * 4,
                 Ag + (long long)(m0 + m) * HH + k0 + kq * 4);
        }
#pragma unroll
        for (int u = 0; u < 4; ++u) {
            int idx = tid + u * 256;
            int k = idx >> 5, nq = idx & 31;
            cp16(sB[buf] + (uint32_t)(k * 132 + nq * 4) * 4,
                 Bg + (long long)(k0 + k) * HH + n0 + nq * 4);
        }
        cp_commit();
    };

    load_stage(0);
#pragma unroll 1
    for (int it = 0; it < NIT; ++it) {
        if (it + 1 < NIT) { load_stage(it + 1); cp_wait<1>(); }
        else              { cp_wait<0>(); }
        __syncthreads();
        int buf = it & 1;
        const float* As = Asb[buf];
        const float* Bs = Bsb[buf];
#pragma unroll
        for (int ks = 0; ks < 4; ++ks) {
            uint32_t af[4][4], bf[4][2];
#pragma unroll
            for (int i = 0; i < 4; ++i) {
                int r0 = wm + i * 16 + g;
                int col = ks * 8 + t;
                af[i][0] = __float_as_uint(As[r0 * 36 + col]);
                af[i][1] = __float_as_uint(As[(r0 + 8) * 36 + col]);
                af[i][2] = __float_as_uint(As[r0 * 36 + col + 4]);
                af[i][3] = __float_as_uint(As[(r0 + 8) * 36 + col + 4]);
            }
#pragma unroll
            for (int j = 0; j < 4; ++j) {
                int nn = wn + j * 8 + g;
                bf[j][0] = __float_as_uint(Bs[(ks * 8 + t) * 132 + nn]);
                bf[j][1] = __float_as_uint(Bs[(ks * 8 + t + 4) * 132 + nn]);
            }
#pragma unroll
            for (int i = 0; i < 4; ++i)
#pragma unroll
                for (int j = 0; j < 4; ++j) mma_tf32(c[i][j], af[i], bf[j]);
        }
        __syncthreads();
    }

    if (!REDUCE) {
        // epilogue: + (b1+b2), round to tf32, store Z
#pragma unroll
        for (int j = 0; j < 4; ++j) {
            int col = n0 + wn + j * 8 + t * 2;
            float bx = bias1[a * HH + col]     + bias2[a * HH + col];
            float by = bias1[a * HH + col + 1] + bias2[a * HH + col + 1];
#pragma unroll
            for (int i = 0; i < 4; ++i) {
                int row = m0 + wm + i * 16 + g;
                float2 v0 = make_float2(f2tf_f(c[i][j][0] + bx), f2tf_f(c[i][j][1] + by));
                float2 v1 = make_float2(f2tf_f(c[i][j][2] + bx), f2tf_f(c[i][j][3] + by));
                *(float2*)&outZ[((long long)a * PP + row) * HH + col]     = v0;
                *(float2*)&outZ[((long long)a * PP + row + 8) * HH + col] = v1;
            }
        }
    } else {
        // epilogue: v = relu(c + b3); partials s1=sum v, s2=sum v^2, s3=sum v*gw
        float* red = sm;
        for (int idx = tid; idx < 128 * 8; idx += 256) red[idx] = 0.f;
        __syncthreads();
#pragma unroll
        for (int i = 0; i < 4; ++i) {
#pragma unroll
            for (int gs = 0; gs < 2; ++gs) {
                float s1 = 0.f, s2 = 0.f, sx = 0.f, sy = 0.f, sz = 0.f, sw = 0.f;
#pragma unroll
                for (int j = 0; j < 4; ++j) {
                    int col = n0 + wn + j * 8 + t * 2;
                    float v0 = fmaxf(c[i][j][gs * 2]     + bias1[a * HH + col],     0.f);
                    float v1 = fmaxf(c[i][j][gs * 2 + 1] + bias1[a * HH + col + 1], 0.f);
                    s1 += v0 + v1;
                    s2 += v0 * v0 + v1 * v1;
                    float4 g0 = *(const float4*)&gw[((long long)a * HH + col) * 4];
                    float4 g1 = *(const float4*)&gw[((long long)a * HH + col + 1) * 4];
                    sx += v0 * g0.x + v1 * g1.x;
                    sy += v0 * g0.y + v1 * g1.y;
                    sz += v0 * g0.z + v1 * g1.z;
                    sw += v0 * g0.w + v1 * g1.w;
                }
#pragma unroll
                for (int o = 1; o <= 2; o <<= 1) {
                    s1 += __shfl_xor_sync(0xFFFFFFFFu, s1, o);
                    s2 += __shfl_xor_sync(0xFFFFFFFFu, s2, o);
                    sx += __shfl_xor_sync(0xFFFFFFFFu, sx, o);
                    sy += __shfl_xor_sync(0xFFFFFFFFu, sy, o);
                    sz += __shfl_xor_sync(0xFFFFFFFFu, sz, o);
                    sw += __shfl_xor_sync(0xFFFFFFFFu, sw, o);
                }
                if (t == 0) {
                    int rl = wm + i * 16 + gs * 8 + g;
                    atomicAdd(&red[rl * 8 + 0], s1);
                    atomicAdd(&red[rl * 8 + 1], s2);
                    atomicAdd(&red[rl * 8 + 2], sx);
                    atomicAdd(&red[rl * 8 + 3], sy);
                    atomicAdd(&red[rl * 8 + 4], sz);
                    atomicAdd(&red[rl * 8 + 5], sw);
                }
            }
        }
        __syncthreads();
        for (int idx = tid; idx < 128 * 6; idx += 256) {
            int row = idx / 6, q = idx % 6;
            part[(((long long)a * 8 + blockIdx.y) * PP + (m0 + row)) * 8 + q] = red[row * 8 + q];
        }
    }
}

// ---------------- final: combine partials, closed-form LN + projection ----------------
__global__ void final_kernel(const float* __restrict__ part, const float* __restrict__ Gco,
                             const float* __restrict__ Bco, float* __restrict__ out) {
    int tk = blockIdx.x * 256 + threadIdx.x;
    int p = tk >> 4, a = tk & 15;
    float s1 = 0.f, s2 = 0.f, so[4] = {0.f, 0.f, 0.f, 0.f};
#pragma unroll
    for (int nt = 0; nt < 8; ++nt) {
        const float* q = part + (((long long)a * 8 + nt) * PP + p) * 8;
        s1 += q[0]; s2 += q[1];
        so[0] += q[2]; so[1] += q[3]; so[2] += q[4]; so[3] += q[5];
    }
    float mu  = s1 * (1.0f / HH);
    float var = s2 * (1.0f / HH) - mu * mu;
    float inv = rsqrtf(var + 1e-5f);
    float4 o;
    o.x = (so[0] - mu * Gco[a * 4 + 0]) * inv + Bco[a * 4 + 0];
    o.y = (so[1] - mu * Gco[a * 4 + 1]) * inv + Bco[a * 4 + 1];
    o.z = (so[2] - mu * Gco[a * 4 + 2]) * inv + Bco[a * 4 + 2];
    o.w = (so[3] - mu * Gco[a * 4 + 3]) * inv + Bco[a * 4 + 3];
    ((float4*)out)[tk] = o;
}

// ---------------- host ----------------
extern "C" void kernel_launch(void* const* d_in, const int* in_sizes, int n_in,
                              void* d_out, int out_size) {
    const float* X     = (const float*)d_in[0];
    const float* X1    = (const float*)d_in[1];
    const float* W1    = (const float*)d_in[2];
    const float* b1    = (const float*)d_in[3];
    const float* W2    = (const float*)d_in[4];
    const float* b2    = (const float*)d_in[5];
    const float* W3    = (const float*)d_in[6];
    const float* b3    = (const float*)d_in[7];
    const float* gamma = (const float*)d_in[8];
    const float* beta  = (const float*)d_in[9];
    const float* W4    = (const float*)d_in[10];
    const float* b4    = (const float*)d_in[11];
    const int*   pos   = (const int*)d_in[12];
    float* out = (float*)d_out;

    float *pXg, *pX1g, *pW, *pZ, *pgw, *pGco, *pBco, *ppart;
    cudaGetSymbolAddress((void**)&pXg,   g_Xg);
    cudaGetSymbolAddress((void**)&pX1g,  g_X1g);
    cudaGetSymbolAddress((void**)&pW,    g_W);
    cudaGetSymbolAddress((void**)&pZ,    g_Z);
    cudaGetSymbolAddress((void**)&pgw,   g_gw);
    cudaGetSymbolAddress((void**)&pGco,  g_Gco);
    cudaGetSymbolAddress((void**)&pBco,  g_Bco);
    cudaGetSymbolAddress((void**)&ppart, g_part);

    cudaFuncSetAttribute(gemm_mma<true,  false>, cudaFuncAttributeMaxDynamicSharedMemorySize, SMEM_BYTES);
    cudaFuncSetAttribute(gemm_mma<false, true >, cudaFuncAttributeMaxDynamicSharedMemorySize, SMEM_BYTES);

    gather_kernel<<<PP, 256>>>(X, X1, pos, pXg, pX1g);
    {
        long long nq = 3ll * AA * HH * HH / 4;     // float4 count
        round_w_kernel<<<(unsigned)(nq / 256), 256>>>(W1, W2, W3, pW);
    }
    prep_kernel<<<AA, 256>>>(gamma, beta, W4, b4, pgw, pGco, pBco);

    const float* W1r = pW;
    const float* W2r = pW + 1ll * AA * HH * HH;
    const float* W3r = pW + 2ll * AA * HH * HH;

    dim3 gg(PP / BM, HH / BN, AA);
    gemm_mma<true, false><<<gg, 256, SMEM_BYTES>>>(
        pXg, pX1g, W1r, W2r, 0LL, b1, b2, nullptr, pZ, nullptr);
    gemm_mma<false, true><<<gg, 256, SMEM_BYTES>>>(
        pZ, nullptr, W3r, nullptr, (long long)PP * HH, b3, nullptr, pgw, nullptr, ppart);
    final_kernel<<<(PP * AA) / 256, 256>>>(ppart, pGco, pBco, out);
}